// round 1
// baseline (speedup 1.0000x reference)
#include <cuda_runtime.h>

#define A_DIM 256
#define H_DIM 512
#define S_DIM 1024
#define T_DIM 256
#define B_DIM 4
#define MS (B_DIM * S_DIM)   /* 4096 rows of eh */
#define MT (B_DIM * T_DIM)   /* 1024 rows of dh */

// Scratch (allocation-free rule: __device__ globals)
__device__ float g_ehT[A_DIM * MS];   // [A][B*S]  (transposed for coalesced s-loads)
__device__ float g_dh[MT * A_DIM];    // [B*T][A]

__device__ __forceinline__ float tanh_fast(float x) {
    float y;
    asm("tanh.approx.f32 %0, %1;" : "=f"(y) : "f"(x));
    return y;
}

// C = X[M,K] @ W[K,N] + bias[N].
// TRANS=true: store C^T at out[n*ldT + m]; else out[m*N + n].
template <bool TRANS>
__global__ __launch_bounds__(256) void gemm_bias_kernel(
    const float* __restrict__ X, const float* __restrict__ W,
    const float* __restrict__ bias, float* __restrict__ out,
    int M, int K, int N, int ldT)
{
    const int BM = 64, BN = 64, BK = 16;
    __shared__ float Xs[BK][BM];
    __shared__ float Ws[BK][BN];

    int tid = threadIdx.x;
    int m0 = blockIdx.x * BM;
    int n0 = blockIdx.y * BN;
    int row = (tid / 16) * 4;
    int col = (tid % 16) * 4;

    float acc[4][4];
#pragma unroll
    for (int i = 0; i < 4; i++)
#pragma unroll
        for (int j = 0; j < 4; j++) acc[i][j] = 0.f;

    for (int k0 = 0; k0 < K; k0 += BK) {
        // Load X tile 64x16 (float4 along K), store transposed into Xs[k][m]
        {
            int m  = tid / 4;           // 0..63
            int k4 = (tid % 4) * 4;     // 0,4,8,12
            float4 v = *(const float4*)&X[(size_t)(m0 + m) * K + k0 + k4];
            Xs[k4 + 0][m] = v.x;
            Xs[k4 + 1][m] = v.y;
            Xs[k4 + 2][m] = v.z;
            Xs[k4 + 3][m] = v.w;
        }
        // Load W tile 16x64 (float4 along N)
        {
            int k  = tid / 16;          // 0..15
            int n4 = (tid % 16) * 4;
            *(float4*)&Ws[k][n4] = *(const float4*)&W[(size_t)(k0 + k) * N + n0 + n4];
        }
        __syncthreads();

#pragma unroll
        for (int kk = 0; kk < BK; kk++) {
            float4 av = *(const float4*)&Xs[kk][row];
            float4 bv = *(const float4*)&Ws[kk][col];
            float ar[4] = {av.x, av.y, av.z, av.w};
            float br[4] = {bv.x, bv.y, bv.z, bv.w};
#pragma unroll
            for (int i = 0; i < 4; i++)
#pragma unroll
                for (int j = 0; j < 4; j++) acc[i][j] += ar[i] * br[j];
        }
        __syncthreads();
    }

#pragma unroll
    for (int j = 0; j < 4; j++) {
        float bj = bias[n0 + col + j];
#pragma unroll
        for (int i = 0; i < 4; i++) {
            float v = acc[i][j] + bj;
            if (TRANS)
                out[(size_t)(n0 + col + j) * ldT + (m0 + row + i)] = v;
            else
                out[(size_t)(m0 + row + i) * N + (n0 + col + j)] = v;
        }
    }
}

// Fused scores + softmax. One block = (b, 4 consecutive t). 256 threads.
// Each thread owns 4 consecutive s (via float4 loads of eh^T), accumulates
// score[t][s] = sum_a Wv[a] * tanh(eh[s][a] + dh[t][a]); bv dropped
// (constant shift is softmax-invariant). Then per-t block softmax over S.
#define TT 4
__global__ __launch_bounds__(256) void attn_softmax_kernel(
    const float* __restrict__ Wv, float* __restrict__ out)
{
    __shared__ float sdh[TT][A_DIM];
    __shared__ float swv[A_DIM];
    __shared__ float red[8];

    int b  = blockIdx.y;
    int t0 = blockIdx.x * TT;
    int tid = threadIdx.x;

    for (int i = tid; i < TT * A_DIM; i += 256) {
        int t = i / A_DIM, a = i % A_DIM;
        sdh[t][a] = g_dh[(size_t)(b * T_DIM + t0 + t) * A_DIM + a];
    }
    if (tid < A_DIM) swv[tid] = Wv[tid];
    __syncthreads();

    int w = tid >> 5, l = tid & 31;
    int sb = w * 128 + l * 4;                 // this thread's 4 s-values
    const float* ehp = &g_ehT[(size_t)b * S_DIM + sb];

    float acc[TT][4];
#pragma unroll
    for (int t = 0; t < TT; t++)
#pragma unroll
        for (int j = 0; j < 4; j++) acc[t][j] = 0.f;

#pragma unroll 4
    for (int a = 0; a < A_DIM; a++) {
        float4 e = *(const float4*)(ehp + (size_t)a * MS);
        float wv = swv[a];
#pragma unroll
        for (int t = 0; t < TT; t++) {
            float d = sdh[t][a];
            acc[t][0] += wv * tanh_fast(e.x + d);
            acc[t][1] += wv * tanh_fast(e.y + d);
            acc[t][2] += wv * tanh_fast(e.z + d);
            acc[t][3] += wv * tanh_fast(e.w + d);
        }
    }

#pragma unroll
    for (int t = 0; t < TT; t++) {
        // block max over S
        float m = fmaxf(fmaxf(acc[t][0], acc[t][1]), fmaxf(acc[t][2], acc[t][3]));
#pragma unroll
        for (int o = 16; o > 0; o >>= 1) m = fmaxf(m, __shfl_xor_sync(0xffffffffu, m, o));
        if (l == 0) red[w] = m;
        __syncthreads();
        float bm = red[0];
#pragma unroll
        for (int i = 1; i < 8; i++) bm = fmaxf(bm, red[i]);
        __syncthreads();

        float e0 = __expf(acc[t][0] - bm);
        float e1 = __expf(acc[t][1] - bm);
        float e2 = __expf(acc[t][2] - bm);
        float e3 = __expf(acc[t][3] - bm);
        float s = e0 + e1 + e2 + e3;
#pragma unroll
        for (int o = 16; o > 0; o >>= 1) s += __shfl_xor_sync(0xffffffffu, s, o);
        if (l == 0) red[w] = s;
        __syncthreads();
        float bsum = red[0];
#pragma unroll
        for (int i = 1; i < 8; i++) bsum += red[i];
        __syncthreads();

        float inv = 1.f / bsum;
        float4 o4 = make_float4(e0 * inv, e1 * inv, e2 * inv, e3 * inv);
        *(float4*)&out[(size_t)(b * T_DIM + t0 + t) * S_DIM + sb] = o4;
    }
}

extern "C" void kernel_launch(void* const* d_in, const int* in_sizes, int n_in,
                              void* d_out, int out_size)
{
    const float* enc = (const float*)d_in[0];  // [4,1024,512]
    const float* dec = (const float*)d_in[1];  // [4,256,512]
    const float* Wh  = (const float*)d_in[2];  // [512,256]
    const float* bh  = (const float*)d_in[3];  // [256]
    const float* Ws  = (const float*)d_in[4];  // [512,256]
    const float* bs  = (const float*)d_in[5];  // [256]
    const float* Wv  = (const float*)d_in[6];  // [256,1]
    // d_in[7] = bv: softmax-invariant shift, unused.
    float* out = (float*)d_out;                // [4,256,1024]

    float* ehT;
    float* dh;
    cudaGetSymbolAddress((void**)&ehT, g_ehT);
    cudaGetSymbolAddress((void**)&dh, g_dh);

    dim3 blk(256);
    dim3 g1(MS / 64, A_DIM / 64);   // 64 x 4
    gemm_bias_kernel<true><<<g1, blk>>>(enc, Wh, bh, ehT, MS, H_DIM, A_DIM, MS);
    dim3 g2(MT / 64, A_DIM / 64);   // 16 x 4
    gemm_bias_kernel<false><<<g2, blk>>>(dec, Ws, bs, dh, MT, H_DIM, A_DIM, 0);
    dim3 g3(T_DIM / TT, B_DIM);     // 64 x 4
    attn_softmax_kernel<<<g3, blk>>>(Wv, out);
}

// round 2
// speedup vs baseline: 1.1046x; 1.1046x over previous
#include <cuda_runtime.h>

#define A_DIM 256
#define H_DIM 512
#define S_DIM 1024
#define T_DIM 256
#define B_DIM 4
#define MS (B_DIM * S_DIM)   /* 4096 rows of eh */
#define MT (B_DIM * T_DIM)   /* 1024 rows of dh */

// Scratch (allocation-free rule: __device__ globals)
__device__ float g_ehT[A_DIM * MS];   // [A][B*S]  (transposed for coalesced s-loads)
__device__ float g_dh[MT * A_DIM];    // [B*T][A]

__device__ __forceinline__ float tanh_fast(float x) {
    float y;
    asm("tanh.approx.f32 %0, %1;" : "=f"(y) : "f"(x));
    return y;
}

// Both GEMMs in ONE launch so they overlap:
//   blockIdx.x <  64 : ehT^T = (enc @ Wh + bh)^T   (M=4096)
//   blockIdx.x >= 64 : dh    =  dec @ Ws + bs      (M=1024)
// BM=64, BN=64, BK=16, 128 threads, 8x4 per-thread tile (less LDS/FMA than 4x4).
__global__ __launch_bounds__(128) void dual_gemm_kernel(
    const float* __restrict__ enc, const float* __restrict__ dec,
    const float* __restrict__ Wh,  const float* __restrict__ bh,
    const float* __restrict__ Wsm, const float* __restrict__ bsm,
    float* __restrict__ ehT, float* __restrict__ dh)
{
    const int BK = 16;
    __shared__ float Xs[BK][64];
    __shared__ float Wt[BK][64];

    bool p2 = blockIdx.x >= 64;
    const float* X    = p2 ? dec : enc;
    const float* W    = p2 ? Wsm : Wh;
    const float* bias = p2 ? bsm : bh;
    int m0 = (p2 ? (blockIdx.x - 64) : blockIdx.x) * 64;
    int n0 = blockIdx.y * 64;
    const int K = H_DIM, N = A_DIM;

    int tid  = threadIdx.x;
    int trow = (tid >> 4) * 8;   // 8 rows per thread
    int tcol = (tid & 15) * 4;   // 4 cols per thread

    float acc[8][4];
#pragma unroll
    for (int i = 0; i < 8; i++)
#pragma unroll
        for (int j = 0; j < 4; j++) acc[i][j] = 0.f;

    // loader mapping
    int lm = tid >> 1;           // 0..63 (row of X tile)
    int lk = (tid & 1) * 8;      // 0 or 8 (32B contiguous per thread)
    int wk = tid >> 3;           // 0..15 (row of W tile)
    int wn = (tid & 7) * 8;      // 0..56

    for (int k0 = 0; k0 < K; k0 += BK) {
        float4 x0 = *(const float4*)&X[(size_t)(m0 + lm) * K + k0 + lk];
        float4 x1 = *(const float4*)&X[(size_t)(m0 + lm) * K + k0 + lk + 4];
        Xs[lk + 0][lm] = x0.x; Xs[lk + 1][lm] = x0.y;
        Xs[lk + 2][lm] = x0.z; Xs[lk + 3][lm] = x0.w;
        Xs[lk + 4][lm] = x1.x; Xs[lk + 5][lm] = x1.y;
        Xs[lk + 6][lm] = x1.z; Xs[lk + 7][lm] = x1.w;
        *(float4*)&Wt[wk][wn]     = *(const float4*)&W[(size_t)(k0 + wk) * N + n0 + wn];
        *(float4*)&Wt[wk][wn + 4] = *(const float4*)&W[(size_t)(k0 + wk) * N + n0 + wn + 4];
        __syncthreads();

#pragma unroll
        for (int kk = 0; kk < BK; kk++) {
            float4 a0 = *(const float4*)&Xs[kk][trow];
            float4 a1 = *(const float4*)&Xs[kk][trow + 4];
            float4 bvv = *(const float4*)&Wt[kk][tcol];
            float ar[8] = {a0.x, a0.y, a0.z, a0.w, a1.x, a1.y, a1.z, a1.w};
            float br[4] = {bvv.x, bvv.y, bvv.z, bvv.w};
#pragma unroll
            for (int i = 0; i < 8; i++)
#pragma unroll
                for (int j = 0; j < 4; j++) acc[i][j] += ar[i] * br[j];
        }
        __syncthreads();
    }

    float bj[4];
#pragma unroll
    for (int j = 0; j < 4; j++) bj[j] = bias[n0 + tcol + j];

    if (!p2) {
        // transposed store: ehT[n][m]
#pragma unroll
        for (int j = 0; j < 4; j++) {
            size_t base = (size_t)(n0 + tcol + j) * MS + m0 + trow;
            float4 v0 = make_float4(acc[0][j] + bj[j], acc[1][j] + bj[j],
                                    acc[2][j] + bj[j], acc[3][j] + bj[j]);
            float4 v1 = make_float4(acc[4][j] + bj[j], acc[5][j] + bj[j],
                                    acc[6][j] + bj[j], acc[7][j] + bj[j]);
            *(float4*)&ehT[base]     = v0;
            *(float4*)&ehT[base + 4] = v1;
        }
    } else {
#pragma unroll
        for (int i = 0; i < 8; i++) {
            float4 v = make_float4(acc[i][0] + bj[0], acc[i][1] + bj[1],
                                   acc[i][2] + bj[2], acc[i][3] + bj[3]);
            *(float4*)&dh[(size_t)(m0 + trow + i) * A_DIM + n0 + tcol] = v;
        }
    }
}

// Fused scores + softmax. One block = (b, 4 consecutive t). 512 threads,
// each thread owns 2 consecutive s (float2 loads of eh^T). 27 warps/SM
// feeds the MUFU pipe (tanh) at its throughput limit.
#define TT 4
__global__ __launch_bounds__(512) void attn_softmax_kernel(
    const float* __restrict__ Wv, float* __restrict__ out)
{
    __shared__ float sdh[TT][A_DIM];
    __shared__ float swv[A_DIM];
    __shared__ float red[16];

    int b   = blockIdx.y;
    int t0  = blockIdx.x * TT;
    int tid = threadIdx.x;

    for (int i = tid; i < TT * A_DIM; i += 512) {
        int t = i / A_DIM, a = i % A_DIM;
        sdh[t][a] = g_dh[(size_t)(b * T_DIM + t0 + t) * A_DIM + a];
    }
    if (tid < A_DIM) swv[tid] = Wv[tid];
    __syncthreads();

    int w = tid >> 5, l = tid & 31;
    int sb = tid * 2;                          // this thread's 2 s-values
    const float* ehp = &g_ehT[(size_t)b * S_DIM + sb];

    float acc[TT][2];
#pragma unroll
    for (int t = 0; t < TT; t++) { acc[t][0] = 0.f; acc[t][1] = 0.f; }

#pragma unroll 8
    for (int a = 0; a < A_DIM; a++) {
        float2 e = *(const float2*)(ehp + (size_t)a * MS);
        float wv = swv[a];
#pragma unroll
        for (int t = 0; t < TT; t++) {
            float d = sdh[t][a];
            acc[t][0] += wv * tanh_fast(e.x + d);
            acc[t][1] += wv * tanh_fast(e.y + d);
        }
    }

#pragma unroll
    for (int t = 0; t < TT; t++) {
        float m = fmaxf(acc[t][0], acc[t][1]);
#pragma unroll
        for (int o = 16; o > 0; o >>= 1) m = fmaxf(m, __shfl_xor_sync(0xffffffffu, m, o));
        if (l == 0) red[w] = m;
        __syncthreads();
        float bm = red[0];
#pragma unroll
        for (int i = 1; i < 16; i++) bm = fmaxf(bm, red[i]);
        __syncthreads();

        float e0 = __expf(acc[t][0] - bm);
        float e1 = __expf(acc[t][1] - bm);
        float s = e0 + e1;
#pragma unroll
        for (int o = 16; o > 0; o >>= 1) s += __shfl_xor_sync(0xffffffffu, s, o);
        if (l == 0) red[w] = s;
        __syncthreads();
        float bsum = red[0];
#pragma unroll
        for (int i = 1; i < 16; i++) bsum += red[i];
        __syncthreads();

        float inv = 1.f / bsum;
        *(float2*)&out[(size_t)(b * T_DIM + t0 + t) * S_DIM + sb] =
            make_float2(e0 * inv, e1 * inv);
    }
}

extern "C" void kernel_launch(void* const* d_in, const int* in_sizes, int n_in,
                              void* d_out, int out_size)
{
    const float* enc = (const float*)d_in[0];  // [4,1024,512]
    const float* dec = (const float*)d_in[1];  // [4,256,512]
    const float* Wh  = (const float*)d_in[2];  // [512,256]
    const float* bh  = (const float*)d_in[3];  // [256]
    const float* Ws  = (const float*)d_in[4];  // [512,256]
    const float* bs  = (const float*)d_in[5];  // [256]
    const float* Wv  = (const float*)d_in[6];  // [256,1]
    // d_in[7] = bv: softmax-invariant shift, unused.
    float* out = (float*)d_out;                // [4,256,1024]

    float* ehT;
    float* dh;
    cudaGetSymbolAddress((void**)&ehT, g_ehT);
    cudaGetSymbolAddress((void**)&dh, g_dh);

    dim3 g1(64 + 16, A_DIM / 64);              // 80 x 4 = 320 CTAs, both GEMMs
    dual_gemm_kernel<<<g1, 128>>>(enc, dec, Wh, bh, Ws, bs, ehT, dh);

    dim3 g3(T_DIM / TT, B_DIM);                // 64 x 4 = 256 CTAs
    attn_softmax_kernel<<<g3, 512>>>(Wv, out);
}

// round 3
// speedup vs baseline: 1.3819x; 1.2511x over previous
#include <cuda_runtime.h>

#define A_DIM 256
#define H_DIM 512
#define S_DIM 1024
#define T_DIM 256
#define B_DIM 4
#define MS (B_DIM * S_DIM)   /* 4096 rows of eh */
#define MT (B_DIM * T_DIM)   /* 1024 rows of dh */

__device__ float g_ehT[A_DIM * MS];   // [A][B*S]
__device__ float g_dh[MT * A_DIM];    // [B*T][A]

__device__ __forceinline__ float tanh_fast(float x) {
    float y;
    asm("tanh.approx.f32 %0, %1;" : "=f"(y) : "f"(x));
    return y;
}

// packed dual-fp32 FMA: d = a*b + d  (Blackwell f32x2, 2x FFMA throughput)
__device__ __forceinline__ void ffma2(float2& d, const float2 a, const float2 b) {
    unsigned long long ud, ua, ub;
    ud = *(const unsigned long long*)&d;
    ua = *(const unsigned long long*)&a;
    ub = *(const unsigned long long*)&b;
    asm("fma.rn.f32x2 %0, %1, %2, %0;" : "+l"(ud) : "l"(ua), "l"(ub));
    *(unsigned long long*)&d = ud;
}

// Both GEMMs in ONE launch:
//   blockIdx.x <  64 : ehT = (enc @ Wh + bh)^T   (M=4096)
//   blockIdx.x >= 64 : dh  =  dec @ Ws + bs      (M=1024)
// BM=64, BN=64, BK=16, 128 threads, 8x4 per-thread tile computed as
// 4 row-pairs x 4 cols via fma.rn.f32x2 (a-pairs packed, b duplicated).
__global__ __launch_bounds__(128) void dual_gemm_kernel(
    const float* __restrict__ enc, const float* __restrict__ dec,
    const float* __restrict__ Wh,  const float* __restrict__ bh,
    const float* __restrict__ Wsm, const float* __restrict__ bsm,
    float* __restrict__ ehT, float* __restrict__ dh)
{
    const int BK = 16;
    __shared__ float Xs[BK][64];
    __shared__ float Wt[BK][64];

    bool p2 = blockIdx.x >= 64;
    const float* X    = p2 ? dec : enc;
    const float* W    = p2 ? Wsm : Wh;
    const float* bias = p2 ? bsm : bh;
    int m0 = (p2 ? (blockIdx.x - 64) : blockIdx.x) * 64;
    int n0 = blockIdx.y * 64;
    const int K = H_DIM, N = A_DIM;

    int tid  = threadIdx.x;
    int trow = (tid >> 4) * 8;   // 8 rows (4 pairs) per thread
    int tcol = (tid & 15) * 4;   // 4 cols per thread

    float2 acc[4][4];            // [row-pair][col]; .x = even row, .y = odd row
#pragma unroll
    for (int p = 0; p < 4; p++)
#pragma unroll
        for (int j = 0; j < 4; j++) acc[p][j] = make_float2(0.f, 0.f);

    int lm = tid >> 1;           // 0..63
    int lk = (tid & 1) * 8;      // 0 or 8
    int wk = tid >> 3;           // 0..15
    int wn = (tid & 7) * 8;      // 0..56

    for (int k0 = 0; k0 < K; k0 += BK) {
        float4 x0 = *(const float4*)&X[(size_t)(m0 + lm) * K + k0 + lk];
        float4 x1 = *(const float4*)&X[(size_t)(m0 + lm) * K + k0 + lk + 4];
        Xs[lk + 0][lm] = x0.x; Xs[lk + 1][lm] = x0.y;
        Xs[lk + 2][lm] = x0.z; Xs[lk + 3][lm] = x0.w;
        Xs[lk + 4][lm] = x1.x; Xs[lk + 5][lm] = x1.y;
        Xs[lk + 6][lm] = x1.z; Xs[lk + 7][lm] = x1.w;
        *(float4*)&Wt[wk][wn]     = *(const float4*)&W[(size_t)(k0 + wk) * N + n0 + wn];
        *(float4*)&Wt[wk][wn + 4] = *(const float4*)&W[(size_t)(k0 + wk) * N + n0 + wn + 4];
        __syncthreads();

#pragma unroll
        for (int kk = 0; kk < BK; kk++) {
            // a row-pairs: 4 float2 straight out of shared
            float2 ap0 = *(const float2*)&Xs[kk][trow];
            float2 ap1 = *(const float2*)&Xs[kk][trow + 2];
            float2 ap2 = *(const float2*)&Xs[kk][trow + 4];
            float2 ap3 = *(const float2*)&Xs[kk][trow + 6];
            float4 bvv = *(const float4*)&Wt[kk][tcol];
            float2 bd[4] = { make_float2(bvv.x, bvv.x), make_float2(bvv.y, bvv.y),
                             make_float2(bvv.z, bvv.z), make_float2(bvv.w, bvv.w) };
#pragma unroll
            for (int j = 0; j < 4; j++) {
                ffma2(acc[0][j], ap0, bd[j]);
                ffma2(acc[1][j], ap1, bd[j]);
                ffma2(acc[2][j], ap2, bd[j]);
                ffma2(acc[3][j], ap3, bd[j]);
            }
        }
        __syncthreads();
    }

    float bj[4];
#pragma unroll
    for (int j = 0; j < 4; j++) bj[j] = bias[n0 + tcol + j];

    if (!p2) {
        // transposed store: ehT[n][m], rows trow..trow+7 contiguous
#pragma unroll
        for (int j = 0; j < 4; j++) {
            size_t base = (size_t)(n0 + tcol + j) * MS + m0 + trow;
            float4 v0 = make_float4(acc[0][j].x + bj[j], acc[0][j].y + bj[j],
                                    acc[1][j].x + bj[j], acc[1][j].y + bj[j]);
            float4 v1 = make_float4(acc[2][j].x + bj[j], acc[2][j].y + bj[j],
                                    acc[3][j].x + bj[j], acc[3][j].y + bj[j]);
            *(float4*)&ehT[base]     = v0;
            *(float4*)&ehT[base + 4] = v1;
        }
    } else {
#pragma unroll
        for (int p = 0; p < 4; p++) {
            float4 ve = make_float4(acc[p][0].x + bj[0], acc[p][1].x + bj[1],
                                    acc[p][2].x + bj[2], acc[p][3].x + bj[3]);
            float4 vo = make_float4(acc[p][0].y + bj[0], acc[p][1].y + bj[1],
                                    acc[p][2].y + bj[2], acc[p][3].y + bj[3]);
            *(float4*)&dh[(size_t)(m0 + trow + 2*p)     * A_DIM + n0 + tcol] = ve;
            *(float4*)&dh[(size_t)(m0 + trow + 2*p + 1) * A_DIM + n0 + tcol] = vo;
        }
    }
}

// Persistent, load-balanced attn+softmax.
// 148 CTAs = 4 batches x 37; each CTA: 1024 threads (thread = one s), owns
// 7 (or 6) consecutive t. dh packed sdh[a][8] -> 2x LDS.128 feeds all t.
// bv dropped (softmax-invariant).
#define CTAS_PER_B 37
#define NT_MAX 7
__global__ __launch_bounds__(1024, 1) void attn_softmax_kernel(
    const float* __restrict__ Wv, float* __restrict__ out)
{
    __shared__ float sdh[A_DIM][8];
    __shared__ float swv[A_DIM];
    __shared__ float redm[32 * 8];
    __shared__ float bmax[8];
    __shared__ float bsum[8];

    int b   = blockIdx.x / CTAS_PER_B;
    int idx = blockIdx.x % CTAS_PER_B;
    int t0, nt;
    if (idx < 34) { t0 = idx * 7;              nt = 7; }
    else          { t0 = 238 + (idx - 34) * 6; nt = 6; }

    int tid = threadIdx.x;
    // fill sdh[a][t]; pad lanes t>=nt clamp to nt-1 (harmless, never stored)
    for (int i = tid; i < A_DIM * 8; i += 1024) {
        int a = i >> 3, t = i & 7;
        int tt = t < nt ? t : nt - 1;
        sdh[a][t] = g_dh[(size_t)(b * T_DIM + t0 + tt) * A_DIM + a];
    }
    if (tid < A_DIM) swv[tid] = Wv[tid];
    __syncthreads();

    int w = tid >> 5, l = tid & 31;
    const float* ehp = &g_ehT[(size_t)b * S_DIM + tid];

    float acc[NT_MAX];
#pragma unroll
    for (int t = 0; t < NT_MAX; t++) acc[t] = 0.f;

#pragma unroll 4
    for (int a = 0; a < A_DIM; a++) {
        float e  = __ldg(ehp + (size_t)a * MS);
        float wv = swv[a];
        float4 d0 = *(const float4*)&sdh[a][0];
        float4 d1 = *(const float4*)&sdh[a][4];
        acc[0] += wv * tanh_fast(e + d0.x);
        acc[1] += wv * tanh_fast(e + d0.y);
        acc[2] += wv * tanh_fast(e + d0.z);
        acc[3] += wv * tanh_fast(e + d0.w);
        acc[4] += wv * tanh_fast(e + d1.x);
        acc[5] += wv * tanh_fast(e + d1.y);
        acc[6] += wv * tanh_fast(e + d1.z);
    }

    // ---- block max per t (warp reduce -> cross-warp reduce by warps 0..6)
#pragma unroll
    for (int t = 0; t < NT_MAX; t++) {
        float m = acc[t];
#pragma unroll
        for (int o = 16; o > 0; o >>= 1) m = fmaxf(m, __shfl_xor_sync(0xffffffffu, m, o));
        if (l == 0) redm[w * 8 + t] = m;
    }
    __syncthreads();
    if (w < NT_MAX) {
        float m = redm[l * 8 + w];
#pragma unroll
        for (int o = 16; o > 0; o >>= 1) m = fmaxf(m, __shfl_xor_sync(0xffffffffu, m, o));
        if (l == 0) bmax[w] = m;
    }
    __syncthreads();

    // ---- exp + block sum per t
    float ex[NT_MAX];
#pragma unroll
    for (int t = 0; t < NT_MAX; t++) {
        ex[t] = __expf(acc[t] - bmax[t]);
        float s = ex[t];
#pragma unroll
        for (int o = 16; o > 0; o >>= 1) s += __shfl_xor_sync(0xffffffffu, s, o);
        if (l == 0) redm[w * 8 + t] = s;
    }
    __syncthreads();
    if (w < NT_MAX) {
        float s = redm[l * 8 + w];
#pragma unroll
        for (int o = 16; o > 0; o >>= 1) s += __shfl_xor_sync(0xffffffffu, s, o);
        if (l == 0) bsum[w] = s;
    }
    __syncthreads();

#pragma unroll
    for (int t = 0; t < NT_MAX; t++) {
        if (t < nt)
            out[(size_t)(b * T_DIM + t0 + t) * S_DIM + tid] = ex[t] * (1.f / bsum[t]);
    }
}

extern "C" void kernel_launch(void* const* d_in, const int* in_sizes, int n_in,
                              void* d_out, int out_size)
{
    const float* enc = (const float*)d_in[0];  // [4,1024,512]
    const float* dec = (const float*)d_in[1];  // [4,256,512]
    const float* Wh  = (const float*)d_in[2];  // [512,256]
    const float* bh  = (const float*)d_in[3];  // [256]
    const float* Ws  = (const float*)d_in[4];  // [512,256]
    const float* bs  = (const float*)d_in[5];  // [256]
    const float* Wv  = (const float*)d_in[6];  // [256,1]
    // d_in[7] = bv: softmax-invariant shift, unused.
    float* out = (float*)d_out;                // [4,256,1024]

    float* ehT;
    float* dh;
    cudaGetSymbolAddress((void**)&ehT, g_ehT);
    cudaGetSymbolAddress((void**)&dh, g_dh);

    dim3 g1(64 + 16, A_DIM / 64);              // 320 CTAs, both GEMMs
    dual_gemm_kernel<<<g1, 128>>>(enc, dec, Wh, bh, Ws, bs, ehT, dh);

    attn_softmax_kernel<<<B_DIM * CTAS_PER_B, 1024>>>(Wv, out);   // 148 CTAs
}